// round 8
// baseline (speedup 1.0000x reference)
#include <cuda_runtime.h>
#include <cuda_bf16.h>

// Problem geometry
#define BATCH   8
#define HIN     1024
#define WIN     1024
#define HC      1025               // code-grid rows
#define WC      1025               // code-grid cols
#define CELLS   (HC * WC)          // 1,050,625 cells per batch
#define WCP     1028               // padded code-row stride (mult of 4)
#define CSTRIDE (HC * WCP)         // per-batch code stride
#define RPB1    8                  // rows per pass1 block
#define NBB1    129                // pass1 chunks per batch: ceil(1025/8)
#define NBLK1   (BATCH * NBB1)     // 1032 pass1 blocks
#define RPB2    2                  // rows per pass2 block (wave balance)
#define NBB2    513                // pass2 chunks per batch: ceil(1025/2)
#define NBLK2   (BATCH * NBB2)     // 4104 pass2 blocks
#define TPB     256
#define NROWS   (2 * BATCH * CELLS)  // 16,810,000 output rows (float4 each)
#define ZSTART  (BATCH * CELLS)      // 8,405,000 = E[total]; pass1 zeros [ZSTART, NROWS)

// -------- scratch (static device globals; no allocation allowed) ----------
__device__ unsigned char g_codes[(size_t)BATCH * CSTRIDE];
__device__ unsigned int  g_cnt1[NBLK2];
__device__ unsigned int  g_cnt2[NBLK2];
__device__ unsigned int  g_off1[NBLK2];
__device__ unsigned int  g_off2[NBLK2];
__device__ unsigned int  g_total;
__device__ unsigned int  g_done;     // zero-init; reset by last block each launch

// Midpoint offsets per code (FIRST table): row = [y+f.x, x+f.y, y+f.z, x+f.w]
__constant__ float4 c_F[16] = {
    { 0.0f,  0.0f,  0.0f,  0.0f},  // 0  (invalid)
    { 0.0f, -0.5f,  0.5f,  0.0f},  // 1
    { 0.5f,  0.0f,  0.0f,  0.5f},  // 2
    { 0.0f, -0.5f,  0.0f,  0.5f},  // 3
    { 0.0f,  0.5f, -0.5f,  0.0f},  // 4
    { 0.0f, -0.5f,  0.5f,  0.0f},  // 5
    { 0.5f,  0.0f, -0.5f,  0.0f},  // 6
    { 0.0f, -0.5f, -0.5f,  0.0f},  // 7
    {-0.5f,  0.0f,  0.0f, -0.5f},  // 8
    {-0.5f,  0.0f,  0.5f,  0.0f},  // 9
    { 0.5f,  0.0f,  0.0f,  0.5f},  // 10
    {-0.5f,  0.0f,  0.0f,  0.5f},  // 11
    { 0.0f,  0.5f,  0.0f, -0.5f},  // 12
    { 0.0f,  0.5f,  0.5f,  0.0f},  // 13
    { 0.5f,  0.0f,  0.0f, -0.5f},  // 14
    { 0.0f,  0.0f,  0.0f,  0.0f},  // 15 (invalid)
};
// SECOND[5] = (0, 0.5, -0.5, 0), SECOND[10] = (-0.5, 0, 0, -0.5) inlined.

// -- Pass 1: codes + counts + speculative tail zero + inline final scan -----
__global__ __launch_bounds__(TPB, 8)
void ms_pass1(const float* __restrict__ in, float* __restrict__ out, int out_size)
{
    float4* __restrict__ out4 = (float4*)out;
    const int bk    = blockIdx.x;
    const int b     = bk / NBB1;
    const int chunk = bk - b * NBB1;
    const int y0    = chunk * RPB1;
    const float* __restrict__ img = in + (size_t)b * HIN * WIN;
    unsigned char* __restrict__ crow0 = g_codes + (size_t)b * CSTRIDE;

    const int t    = threadIdx.x;
    const int col  = 4 * t;                  // 0..1020, float4 covers 4 cols
    const int lane = t & 31;
    const int wid  = t >> 5;
    __shared__ unsigned r1[8], r2[8];

    // initial top row for y0: input row clamp(y0-1, 0, 1023)
    const float* rA = img + (size_t)max(min(y0 - 1, HIN - 1), 0) * WIN;
    float4 vA = *(const float4*)(rA + col);
    float lmA = __shfl_up_sync(0xffffffffu, vA.w, 1);
    if (lane == 0) lmA = (col > 0) ? rA[col - 1] : vA.x;

    #pragma unroll
    for (int sub = 0; sub < 4; sub++) {
        const int ys = y0 + 2 * sub;
        if (ys >= HC) break;                 // uniform across block
        const int ye = min(ys + 2, HC);
        unsigned c1 = 0, c2 = 0;

        for (int y = ys; y < ye; y++) {
            const float* rB = img + (size_t)min(y, HIN - 1) * WIN;
            float4 vB = *(const float4*)(rB + col);
            float lmB = __shfl_up_sync(0xffffffffu, vB.w, 1);
            if (lane == 0) lmB = (col > 0) ? rB[col - 1] : vB.x;

            const float la[4] = {lmA, vA.x, vA.y, vA.z};
            const float ra[4] = {vA.x, vA.y, vA.z, vA.w};
            const float lb[4] = {lmB, vB.x, vB.y, vB.z};
            const float rb[4] = {vB.x, vB.y, vB.z, vB.w};

            unsigned packed = 0;
            #pragma unroll
            for (int j = 0; j < 4; j++) {
                unsigned code = (lb[j] > 0.0f ? 1u : 0u) | (rb[j] > 0.0f ? 2u : 0u) |
                                (ra[j] > 0.0f ? 4u : 0u) | (la[j] > 0.0f ? 8u : 0u);
                packed |= code << (8 * j);
                c1 += (code - 1u) < 14u;
                c2 += (code == 5u) | (code == 10u);
            }
            unsigned char* crow = crow0 + (size_t)y * WCP;
            *(unsigned int*)(crow + col) = packed;
            if (t == TPB - 1) {              // cell x = 1024 (clamped both sides)
                unsigned code = (vB.w > 0.0f ? 3u : 0u) | (vA.w > 0.0f ? 12u : 0u);
                crow[1024] = (unsigned char)code;
                c1 += (code - 1u) < 14u;
            }
            vA = vB; lmA = lmB;              // row reuse: bottom(y) == top(y+1)
        }

        // block reduction for this 2-row subchunk
        unsigned s1 = __reduce_add_sync(0xffffffffu, c1);
        unsigned s2 = __reduce_add_sync(0xffffffffu, c2);
        __syncthreads();                     // r1/r2 reuse safety
        if (lane == 0) { r1[wid] = s1; r2[wid] = s2; }
        __syncthreads();
        if (t == 0) {
            unsigned t1 = 0, t2 = 0;
            #pragma unroll
            for (int i = 0; i < 8; i++) { t1 += r1[i]; t2 += r2[i]; }
            const int idx = b * NBB2 + chunk * 4 + sub;
            g_cnt1[idx] = t1;
            g_cnt2[idx] = t2;
        }
    }

    // ---- speculative zero of [ZSTART, NROWS): rows >= total get final 0;
    //      rows in [ZSTART, total) are legally overwritten by pass2 later ----
    {
        const unsigned zn = (unsigned)(NROWS - ZSTART);
        const unsigned cz = (zn + NBLK1 - 1) / NBLK1;
        const unsigned s  = (unsigned)ZSTART + (unsigned)bk * cz;
        const unsigned e  = min(s + cz, (unsigned)NROWS);
        const float4 z = make_float4(0.0f, 0.0f, 0.0f, 0.0f);
        for (unsigned i = s + t; i < e; i += TPB) __stcs(&out4[i], z);
    }

    // ---- last-block-done: final block performs the global scan inline -----
    __shared__ unsigned slast;
    if (t == 0) {
        __threadfence();                     // publish g_cnt before counter
        const bool last = (atomicAdd(&g_done, 1u) == (unsigned)(NBLK1 - 1));
        if (last) g_done = 0;                // reset for next launch
        slast = last ? 1u : 0u;
    }
    __syncthreads();
    if (!slast) return;
    __threadfence();                         // acquire: see all g_cnt writes

    __shared__ unsigned tot[16], gbs[17];
    // Phase A: totals per group (warp wid handles groups 2*wid, 2*wid+1)
    #pragma unroll
    for (int rep = 0; rep < 2; rep++) {
        const int g = wid * 2 + rep;
        const unsigned* __restrict__ cnt = (g & 1) ? g_cnt2 : g_cnt1;
        const int base = (g >> 1) * NBB2;
        const int i0 = lane * 17;
        unsigned s = 0;
        #pragma unroll
        for (int j = 0; j < 17; j++) {
            const int i = i0 + j;
            if (i < NBB2) s += cnt[base + i];
        }
        s = __reduce_add_sync(0xffffffffu, s);
        if (lane == 0) tot[g] = s;
    }
    __syncthreads();
    if (t == 0) {
        unsigned acc = 0;
        #pragma unroll
        for (int g = 0; g < 16; g++) { gbs[g] = acc; acc += tot[g]; }
        gbs[16] = acc;
        g_total = acc;
    }
    __syncthreads();
    if (t < BATCH && out_size >= NROWS * 4 + BATCH)
        out[(size_t)NROWS * 4 + t] = (float)(tot[2 * t] + tot[2 * t + 1]);

    // Phase C: exclusive offsets (register-resident, 17 entries per lane)
    #pragma unroll
    for (int rep = 0; rep < 2; rep++) {
        const int g = wid * 2 + rep;
        const unsigned* __restrict__ cnt = (g & 1) ? g_cnt2 : g_cnt1;
        unsigned*       __restrict__ off = (g & 1) ? g_off2 : g_off1;
        const int base = (g >> 1) * NBB2;
        const int i0 = lane * 17;
        unsigned v[17];
        unsigned s = 0;
        #pragma unroll
        for (int j = 0; j < 17; j++) {
            const int i = i0 + j;
            v[j] = (i < NBB2) ? cnt[base + i] : 0u;
            s += v[j];
        }
        unsigned incl = s;
        #pragma unroll
        for (int o = 1; o < 32; o <<= 1) {
            const unsigned u = __shfl_up_sync(0xffffffffu, incl, o);
            if (lane >= o) incl += u;
        }
        unsigned run = gbs[g] + incl - s;    // exclusive base for this lane
        #pragma unroll
        for (int j = 0; j < 17; j++) {
            const int i = i0 + j;
            if (i < NBB2) off[base + i] = run;
            run += v[j];
        }
    }
}

// ------ Pass 2: smem-staged row compaction + WT flush + residual zero ------
__global__ __launch_bounds__(TPB)
void ms_pass2(float4* __restrict__ out4)
{
    __shared__ unsigned ws[8];
    __shared__ unsigned sh_n;                 // packed row totals (c1 | c2<<16)
    __shared__ float4 buf1[1026];
    __shared__ float4 buf2[1026];

    const int bk   = blockIdx.x;
    const int b    = bk / NBB2;
    const int ci   = bk - b * NBB2;
    const int y0   = ci * RPB2;
    const int nrows = min(y0 + RPB2, HC) - y0;
    const unsigned char* __restrict__ crow0 = g_codes + (size_t)b * CSTRIDE;

    const int t = threadIdx.x;
    const unsigned lane = t & 31u, wid = t >> 5;

    unsigned off1 = g_off1[bk];               // uniform across block
    unsigned off2 = g_off2[bk];

    // prefetch both rows' code words (MLP across the two row phases)
    unsigned packs[2], cXs[2];
    #pragma unroll
    for (int r = 0; r < 2; r++) {
        if (r < nrows) {
            const unsigned char* crow = crow0 + (size_t)(y0 + r) * WCP;
            packs[r] = *(const unsigned int*)(crow + 4 * t);
            cXs[r]   = (t == TPB - 1) ? (unsigned)crow[1024] : 0u;
        } else { packs[r] = 0u; cXs[r] = 0u; }
    }

    #pragma unroll
    for (int r = 0; r < 2; r++) {
        if (r >= nrows) break;
        const int y = y0 + r;
        const unsigned packed = packs[r];
        unsigned cd[4];
        cd[0] =  packed        & 255u;
        cd[1] = (packed >>  8) & 255u;
        cd[2] = (packed >> 16) & 255u;
        cd[3] =  packed >> 24;
        const unsigned cX = cXs[r];

        unsigned c1 = 0, c2 = 0;
        #pragma unroll
        for (int j = 0; j < 4; j++) {
            c1 += (cd[j] - 1u) < 14u;
            c2 += (cd[j] == 5u) | (cd[j] == 10u);
        }
        c1 += (cX - 1u) < 14u;

        // block exclusive scan (16-bit packed: c1 | c2<<16)
        const unsigned v = c1 | (c2 << 16);
        unsigned inc = v;
        #pragma unroll
        for (int o = 1; o < 32; o <<= 1) {
            const unsigned u = __shfl_up_sync(0xffffffffu, inc, o);
            if (lane >= (unsigned)o) inc += u;
        }
        if (lane == 31) ws[wid] = inc;
        __syncthreads();
        if (t == 0) {
            unsigned acc = 0;
            #pragma unroll
            for (int i = 0; i < 8; i++) { const unsigned q = ws[i]; ws[i] = acc; acc += q; }
        }
        __syncthreads();
        const unsigned ex = inc - v + ws[wid];
        if (t == TPB - 1) sh_n = ex + v;      // block totals for this row
        unsigned p1 = ex & 0xffffu;
        unsigned p2 = ex >> 16;

        // stage compacted entries into shared memory
        const float fy = (float)y;
        const float fx = (float)(4 * t);
        #pragma unroll
        for (int j = 0; j < 4; j++) {
            const unsigned code = cd[j];
            const float cx = fx + (float)j;
            if ((code - 1u) < 14u) {
                const float4 f = c_F[code];
                buf1[p1++] = make_float4(fy + f.x, cx + f.y, fy + f.z, cx + f.w);
            }
            if (code == 5u)
                buf2[p2++] = make_float4(fy, cx + 0.5f, fy - 0.5f, cx);
            else if (code == 10u)
                buf2[p2++] = make_float4(fy - 0.5f, cx, fy, cx - 0.5f);
        }
        if (t == TPB - 1 && (cX - 1u) < 14u) {
            const float4 f = c_F[cX];
            buf1[p1++] = make_float4(fy + f.x, 1024.0f + f.y, fy + f.z, 1024.0f + f.w);
        }
        __syncthreads();

        // coalesced write-through flush to gmem
        const unsigned n = sh_n;
        const unsigned n1 = n & 0xffffu;
        const unsigned n2 = n >> 16;
        for (unsigned i = t; i < n1; i += TPB) __stwt(&out4[off1 + i], buf1[i]);
        for (unsigned i = t; i < n2; i += TPB) __stwt(&out4[off2 + i], buf2[i]);
        off1 += n1;
        off2 += n2;
        __syncthreads();                      // buffers reused next row
    }

    // residual zero: [g_total, ZSTART) only (pass1 already zeroed the rest)
    const unsigned total = g_total;
    if (total < (unsigned)ZSTART) {
        const unsigned tail = (unsigned)ZSTART - total;
        const unsigned cz   = (tail + NBLK2 - 1) / NBLK2;
        const unsigned s    = total + (unsigned)bk * cz;
        const unsigned e    = min(s + cz, (unsigned)ZSTART);
        const float4 z = make_float4(0.0f, 0.0f, 0.0f, 0.0f);
        for (unsigned i = s + t; i < e; i += TPB) __stwt(&out4[i], z);
    }
}

// ---------------------------------------------------------------------------
extern "C" void kernel_launch(void* const* d_in, const int* in_sizes, int n_in,
                              void* d_out, int out_size)
{
    const float* coarse = (const float*)d_in[0];
    float* out = (float*)d_out;

    ms_pass1<<<NBLK1, TPB>>>(coarse, out, out_size);
    ms_pass2<<<NBLK2, TPB>>>((float4*)out);
}

// round 9
// speedup vs baseline: 1.1352x; 1.1352x over previous
#include <cuda_runtime.h>
#include <cuda_bf16.h>

// Problem geometry
#define BATCH   8
#define HIN     1024
#define WIN     1024
#define HC      1025               // code-grid rows
#define WC      1025               // code-grid cols
#define CELLS   (HC * WC)          // 1,050,625 cells per batch
#define WCP     1028               // padded code-row stride (mult of 4)
#define CSTRIDE (HC * WCP)         // per-batch code stride
#define RPB1    8                  // rows per pass1 block
#define NBB1    129                // pass1 chunks per batch: ceil(1025/8)
#define NBLK1   (BATCH * NBB1)     // 1032 pass1 blocks
#define RPB2    2                  // rows per pass2 block (wave balance)
#define NBB2    513                // pass2 chunks per batch: ceil(1025/2)
#define NBLK2   (BATCH * NBB2)     // 4104 pass2 blocks
#define TPB     256
#define NROWS   (2 * BATCH * CELLS)  // 16,810,000 output rows (float4 each)

// -------- scratch (static device globals; no allocation allowed) ----------
__device__ unsigned char g_codes[(size_t)BATCH * CSTRIDE];
__device__ unsigned int  g_cnt1[NBLK2];
__device__ unsigned int  g_cnt2[NBLK2];
__device__ unsigned int  g_off1[NBLK2];
__device__ unsigned int  g_off2[NBLK2];
__device__ unsigned int  g_total;
__device__ unsigned int  g_done;     // zero-init; reset by last block each launch

// Midpoint offsets per code (FIRST table): row = [y+f.x, x+f.y, y+f.z, x+f.w]
__constant__ float4 c_F[16] = {
    { 0.0f,  0.0f,  0.0f,  0.0f},  // 0  (invalid)
    { 0.0f, -0.5f,  0.5f,  0.0f},  // 1
    { 0.5f,  0.0f,  0.0f,  0.5f},  // 2
    { 0.0f, -0.5f,  0.0f,  0.5f},  // 3
    { 0.0f,  0.5f, -0.5f,  0.0f},  // 4
    { 0.0f, -0.5f,  0.5f,  0.0f},  // 5
    { 0.5f,  0.0f, -0.5f,  0.0f},  // 6
    { 0.0f, -0.5f, -0.5f,  0.0f},  // 7
    {-0.5f,  0.0f,  0.0f, -0.5f},  // 8
    {-0.5f,  0.0f,  0.5f,  0.0f},  // 9
    { 0.5f,  0.0f,  0.0f,  0.5f},  // 10
    {-0.5f,  0.0f,  0.0f,  0.5f},  // 11
    { 0.0f,  0.5f,  0.0f, -0.5f},  // 12
    { 0.0f,  0.5f,  0.5f,  0.0f},  // 13
    { 0.5f,  0.0f,  0.0f, -0.5f},  // 14
    { 0.0f,  0.0f,  0.0f,  0.0f},  // 15 (invalid)
};
// SECOND[5] = (0, 0.5, -0.5, 0), SECOND[10] = (-0.5, 0, 0, -0.5) inlined.

// ------- Pass 1: codes + per-2-row-subchunk counts + inline final scan -----
__global__ __launch_bounds__(TPB, 8)
void ms_pass1(const float* __restrict__ in, float* __restrict__ out, int out_size)
{
    const int bk    = blockIdx.x;
    const int b     = bk / NBB1;
    const int chunk = bk - b * NBB1;
    const int y0    = chunk * RPB1;
    const float* __restrict__ img = in + (size_t)b * HIN * WIN;
    unsigned char* __restrict__ crow0 = g_codes + (size_t)b * CSTRIDE;

    const int t    = threadIdx.x;
    const int col  = 4 * t;                  // 0..1020, float4 covers 4 cols
    const int lane = t & 31;
    const int wid  = t >> 5;
    __shared__ unsigned r1[8], r2[8];

    // initial top row for y0: input row clamp(y0-1, 0, 1023)
    const float* rA = img + (size_t)max(min(y0 - 1, HIN - 1), 0) * WIN;
    float4 vA = *(const float4*)(rA + col);
    float lmA = __shfl_up_sync(0xffffffffu, vA.w, 1);
    if (lane == 0) lmA = (col > 0) ? rA[col - 1] : vA.x;

    #pragma unroll
    for (int sub = 0; sub < 4; sub++) {
        const int ys = y0 + 2 * sub;
        if (ys >= HC) break;                 // uniform across block
        const int ye = min(ys + 2, HC);
        unsigned c1 = 0, c2 = 0;

        for (int y = ys; y < ye; y++) {
            const float* rB = img + (size_t)min(y, HIN - 1) * WIN;
            float4 vB = *(const float4*)(rB + col);
            float lmB = __shfl_up_sync(0xffffffffu, vB.w, 1);
            if (lane == 0) lmB = (col > 0) ? rB[col - 1] : vB.x;

            const float la[4] = {lmA, vA.x, vA.y, vA.z};
            const float ra[4] = {vA.x, vA.y, vA.z, vA.w};
            const float lb[4] = {lmB, vB.x, vB.y, vB.z};
            const float rb[4] = {vB.x, vB.y, vB.z, vB.w};

            unsigned packed = 0;
            #pragma unroll
            for (int j = 0; j < 4; j++) {
                unsigned code = (lb[j] > 0.0f ? 1u : 0u) | (rb[j] > 0.0f ? 2u : 0u) |
                                (ra[j] > 0.0f ? 4u : 0u) | (la[j] > 0.0f ? 8u : 0u);
                packed |= code << (8 * j);
                c1 += (code - 1u) < 14u;
                c2 += (code == 5u) | (code == 10u);
            }
            unsigned char* crow = crow0 + (size_t)y * WCP;
            *(unsigned int*)(crow + col) = packed;
            if (t == TPB - 1) {              // cell x = 1024 (clamped both sides)
                unsigned code = (vB.w > 0.0f ? 3u : 0u) | (vA.w > 0.0f ? 12u : 0u);
                crow[1024] = (unsigned char)code;
                c1 += (code - 1u) < 14u;
            }
            vA = vB; lmA = lmB;              // row reuse: bottom(y) == top(y+1)
        }

        // block reduction for this 2-row subchunk
        unsigned s1 = __reduce_add_sync(0xffffffffu, c1);
        unsigned s2 = __reduce_add_sync(0xffffffffu, c2);
        __syncthreads();                     // r1/r2 reuse safety
        if (lane == 0) { r1[wid] = s1; r2[wid] = s2; }
        __syncthreads();
        if (t == 0) {
            unsigned t1 = 0, t2 = 0;
            #pragma unroll
            for (int i = 0; i < 8; i++) { t1 += r1[i]; t2 += r2[i]; }
            const int idx = b * NBB2 + chunk * 4 + sub;
            g_cnt1[idx] = t1;
            g_cnt2[idx] = t2;
        }
    }

    // ---- last-block-done: final block performs the global scan inline -----
    __shared__ unsigned slast;
    if (t == 0) {
        __threadfence();                     // publish g_cnt before counter
        const bool last = (atomicAdd(&g_done, 1u) == (unsigned)(NBLK1 - 1));
        if (last) g_done = 0;                // reset for next launch
        slast = last ? 1u : 0u;
    }
    __syncthreads();
    if (!slast) return;
    __threadfence();                         // acquire: see all g_cnt writes

    __shared__ unsigned tot[16], gbs[17];
    // Phase A: totals per group (warp wid handles groups 2*wid, 2*wid+1)
    #pragma unroll
    for (int rep = 0; rep < 2; rep++) {
        const int g = wid * 2 + rep;
        const unsigned* __restrict__ cnt = (g & 1) ? g_cnt2 : g_cnt1;
        const int base = (g >> 1) * NBB2;
        const int i0 = lane * 17;
        unsigned s = 0;
        #pragma unroll
        for (int j = 0; j < 17; j++) {
            const int i = i0 + j;
            if (i < NBB2) s += cnt[base + i];
        }
        s = __reduce_add_sync(0xffffffffu, s);
        if (lane == 0) tot[g] = s;
    }
    __syncthreads();
    if (t == 0) {
        unsigned acc = 0;
        #pragma unroll
        for (int g = 0; g < 16; g++) { gbs[g] = acc; acc += tot[g]; }
        gbs[16] = acc;
        g_total = acc;
    }
    __syncthreads();
    if (t < BATCH && out_size >= NROWS * 4 + BATCH)
        out[(size_t)NROWS * 4 + t] = (float)(tot[2 * t] + tot[2 * t + 1]);

    // Phase C: exclusive offsets (register-resident, 17 entries per lane)
    #pragma unroll
    for (int rep = 0; rep < 2; rep++) {
        const int g = wid * 2 + rep;
        const unsigned* __restrict__ cnt = (g & 1) ? g_cnt2 : g_cnt1;
        unsigned*       __restrict__ off = (g & 1) ? g_off2 : g_off1;
        const int base = (g >> 1) * NBB2;
        const int i0 = lane * 17;
        unsigned v[17];
        unsigned s = 0;
        #pragma unroll
        for (int j = 0; j < 17; j++) {
            const int i = i0 + j;
            v[j] = (i < NBB2) ? cnt[base + i] : 0u;
            s += v[j];
        }
        unsigned incl = s;
        #pragma unroll
        for (int o = 1; o < 32; o <<= 1) {
            const unsigned u = __shfl_up_sync(0xffffffffu, incl, o);
            if (lane >= o) incl += u;
        }
        unsigned run = gbs[g] + incl - s;    // exclusive base for this lane
        #pragma unroll
        for (int j = 0; j < 17; j++) {
            const int i = i0 + j;
            if (i < NBB2) off[base + i] = run;
            run += v[j];
        }
    }
}

// -- Pass 2: buf1-only staging (8 CTAs/SM), direct table2 scatter, tail zero -
__global__ __launch_bounds__(TPB, 8)
void ms_pass2(float4* __restrict__ out4)
{
    __shared__ unsigned ws[8];
    __shared__ unsigned sh_n;                 // packed row totals (c1 | c2<<16)
    __shared__ float4 buf1[1026];             // 16.4 KB: table-1 staging only

    const int bk   = blockIdx.x;
    const int b    = bk / NBB2;
    const int ci   = bk - b * NBB2;
    const int y0   = ci * RPB2;
    const int nrows = min(y0 + RPB2, HC) - y0;
    const unsigned char* __restrict__ crow0 = g_codes + (size_t)b * CSTRIDE;

    const int t = threadIdx.x;
    const unsigned lane = t & 31u, wid = t >> 5;

    unsigned off1 = g_off1[bk];               // uniform across block
    unsigned off2 = g_off2[bk];

    // prefetch both rows' code words (MLP across the two row phases)
    unsigned packs[2], cXs[2];
    #pragma unroll
    for (int r = 0; r < 2; r++) {
        if (r < nrows) {
            const unsigned char* crow = crow0 + (size_t)(y0 + r) * WCP;
            packs[r] = *(const unsigned int*)(crow + 4 * t);
            cXs[r]   = (t == TPB - 1) ? (unsigned)crow[1024] : 0u;
        } else { packs[r] = 0u; cXs[r] = 0u; }
    }

    #pragma unroll
    for (int r = 0; r < 2; r++) {
        if (r >= nrows) break;
        const int y = y0 + r;
        const unsigned packed = packs[r];
        unsigned cd[4];
        cd[0] =  packed        & 255u;
        cd[1] = (packed >>  8) & 255u;
        cd[2] = (packed >> 16) & 255u;
        cd[3] =  packed >> 24;
        const unsigned cX = cXs[r];

        unsigned c1 = 0, c2 = 0;
        #pragma unroll
        for (int j = 0; j < 4; j++) {
            c1 += (cd[j] - 1u) < 14u;
            c2 += (cd[j] == 5u) | (cd[j] == 10u);
        }
        c1 += (cX - 1u) < 14u;

        // block exclusive scan (16-bit packed: c1 | c2<<16)
        const unsigned v = c1 | (c2 << 16);
        unsigned inc = v;
        #pragma unroll
        for (int o = 1; o < 32; o <<= 1) {
            const unsigned u = __shfl_up_sync(0xffffffffu, inc, o);
            if (lane >= (unsigned)o) inc += u;
        }
        if (lane == 31) ws[wid] = inc;
        __syncthreads();
        if (t == 0) {
            unsigned acc = 0;
            #pragma unroll
            for (int i = 0; i < 8; i++) { const unsigned q = ws[i]; ws[i] = acc; acc += q; }
        }
        __syncthreads();
        const unsigned ex = inc - v + ws[wid];
        if (t == TPB - 1) sh_n = ex + v;      // block totals for this row
        unsigned p1 = ex & 0xffffu;           // buf1 slot
        unsigned q2 = off2 + (ex >> 16);      // direct gmem position (table 2)

        // stage table-1 entries in smem; scatter sparse table-2 directly
        const float fy = (float)y;
        const float fx = (float)(4 * t);
        #pragma unroll
        for (int j = 0; j < 4; j++) {
            const unsigned code = cd[j];
            const float cx = fx + (float)j;
            if ((code - 1u) < 14u) {
                const float4 f = c_F[code];
                buf1[p1++] = make_float4(fy + f.x, cx + f.y, fy + f.z, cx + f.w);
            }
            if (code == 5u)
                __stwt(&out4[q2++], make_float4(fy, cx + 0.5f, fy - 0.5f, cx));
            else if (code == 10u)
                __stwt(&out4[q2++], make_float4(fy - 0.5f, cx, fy, cx - 0.5f));
        }
        if (t == TPB - 1 && (cX - 1u) < 14u) {
            const float4 f = c_F[cX];
            buf1[p1++] = make_float4(fy + f.x, 1024.0f + f.y, fy + f.z, 1024.0f + f.w);
        }
        __syncthreads();

        // coalesced write-through flush of table-1 entries
        const unsigned n = sh_n;
        const unsigned n1 = n & 0xffffu;
        for (unsigned i = t; i < n1; i += TPB) __stwt(&out4[off1 + i], buf1[i]);
        off1 += n1;
        off2 += (n >> 16);
        __syncthreads();                      // buffer reused next row
    }

    // fused tail zero: this block's slice of [g_total, NROWS)
    const unsigned total = g_total;
    const unsigned tail  = (unsigned)NROWS - total;
    const unsigned cz    = (tail + NBLK2 - 1) / NBLK2;
    const unsigned s     = total + (unsigned)bk * cz;
    const unsigned e     = min(s + cz, (unsigned)NROWS);
    const float4 z = make_float4(0.0f, 0.0f, 0.0f, 0.0f);
    for (unsigned i = s + t; i < e; i += TPB) __stwt(&out4[i], z);
}

// ---------------------------------------------------------------------------
extern "C" void kernel_launch(void* const* d_in, const int* in_sizes, int n_in,
                              void* d_out, int out_size)
{
    const float* coarse = (const float*)d_in[0];
    float* out = (float*)d_out;

    ms_pass1<<<NBLK1, TPB>>>(coarse, out, out_size);
    ms_pass2<<<NBLK2, TPB>>>((float4*)out);
}